// round 13
// baseline (speedup 1.0000x reference)
#include <cuda_runtime.h>

#define G3 (64 * 64 * 64)          // 262144 voxels per batch
#define PAIRS_PER_B (G3 / 2)       // 131072 voxel pairs per batch

typedef unsigned long long u64;

// C0 as plain floats in constant memory — filled by ONE linear 324B memcpy
// node. Lane-duplication for f32x2 happens in-kernel (absorbed into idle
// issue slots; measured free in R10).
__constant__ float C0F[81];

__device__ __forceinline__ u64 f2fma(u64 a, u64 b, u64 c) {
    u64 d; asm("fma.rn.f32x2 %0, %1, %2, %3;" : "=l"(d) : "l"(a), "l"(b), "l"(c)); return d;
}
__device__ __forceinline__ u64 f2mul(u64 a, u64 b) {
    u64 d; asm("mul.rn.f32x2 %0, %1, %2;" : "=l"(d) : "l"(a), "l"(b)); return d;
}
__device__ __forceinline__ u64 f2dup(float x) {
    u64 d; asm("mov.b64 %0, {%1, %1};" : "=l"(d) : "f"(x)); return d;
}

// One thread = one voxel PAIR (v, v+1), all 3 output indices i (rolled loop).
// Identical math to the 30.7us kernel; launch_bounds(128,5) caps regs at 96
// (was 102) -> 5 CTAs/SM = 20 resident warps (+25% latency hiding).
__global__ void __launch_bounds__(128, 5)
alphaC0_kernel(const float* __restrict__ alpha,
               float* __restrict__ out,
               int pairs_total)
{
    const int tid = blockIdx.x * blockDim.x + threadIdx.x;
    if (tid >= pairs_total) return;

    const int b = tid >> 17;                   // / PAIRS_PER_B
    const int v = (tid & (PAIRS_PER_B - 1)) * 2;

    // A2[m][c] = packed { A(v)[m][c], A(v+1)[m][c] }
    u64 A2[3][3];
#pragma unroll
    for (int m = 0; m < 3; m++)
#pragma unroll
        for (int c = 0; c < 3; c++)
            A2[m][c] = *reinterpret_cast<const u64*>(
                &alpha[(size_t)((b * 3 + m) * 3 + c) * G3 + v]);

    const char* outb0 = reinterpret_cast<const char*>(out)
                      + ((size_t)b * 81 * G3 + v) * sizeof(float);

#pragma unroll 1
    for (int i = 0; i < 3; i++) {
        u64 a0, a1, a2;
        if (i == 0)      { a0 = A2[0][0]; a1 = A2[1][0]; a2 = A2[2][0]; }
        else if (i == 1) { a0 = A2[0][1]; a1 = A2[1][1]; a2 = A2[2][1]; }
        else             { a0 = A2[0][2]; a1 = A2[1][2]; a2 = A2[2][2]; }

        // Fused stage1+2: T2[j][o][p] = sum_n A[n][j] * (sum_m a_m C0[m][n][o][p])
        u64 T2[27];
#pragma unroll
        for (int o = 0; o < 3; o++) {
#pragma unroll
            for (int p = 0; p < 3; p++) {
                u64 t1[3];
#pragma unroll
                for (int n = 0; n < 3; n++) {
                    t1[n] = f2fma(a0, f2dup(C0F[((0 * 3 + n) * 3 + o) * 3 + p]),
                            f2fma(a1, f2dup(C0F[((1 * 3 + n) * 3 + o) * 3 + p]),
                            f2mul(a2, f2dup(C0F[((2 * 3 + n) * 3 + o) * 3 + p]))));
                }
#pragma unroll
                for (int j = 0; j < 3; j++) {
                    T2[(j * 3 + o) * 3 + p] =
                        f2fma(A2[0][j], t1[0],
                        f2fma(A2[1][j], t1[1],
                        f2mul(A2[2][j], t1[2])));
                }
            }
        }

        // Fused stage3+4: per (j,k) build t3[p], emit 3 STG.64 immediately
        const char* outb = outb0 + (size_t)(i * 27) * G3 * sizeof(float);
#pragma unroll
        for (int j = 0; j < 3; j++) {
#pragma unroll
            for (int k = 0; k < 3; k++) {
                u64 t3[3];
#pragma unroll
                for (int p = 0; p < 3; p++) {
                    t3[p] = f2fma(A2[0][k], T2[(j * 3 + 0) * 3 + p],
                            f2fma(A2[1][k], T2[(j * 3 + 1) * 3 + p],
                            f2mul(A2[2][k], T2[(j * 3 + 2) * 3 + p])));
                }
#pragma unroll
                for (int l = 0; l < 3; l++) {
                    *reinterpret_cast<u64*>(const_cast<char*>(
                        outb + (size_t)((j * 3 + k) * 3 + l) * G3 * sizeof(float))) =
                        f2fma(A2[0][l], t3[0],
                        f2fma(A2[1][l], t3[1],
                        f2mul(A2[2][l], t3[2])));
                }
            }
        }
    }
}

extern "C" void kernel_launch(void* const* d_in, const int* in_sizes, int n_in,
                              void* d_out, int out_size)
{
    const float* alpha = (const float*)d_in[0];   // (B,3,3,G,G,G) float32
    const float* C0    = (const float*)d_in[1];   // (3,3,3,3) float32
    float* out         = (float*)d_out;           // (B,3,3,3,3,G,G,G) float32

    // Single linear 324B D2D memcpy into the constant bank (graph memcpy node).
    cudaMemcpyToSymbolAsync(C0F, C0, 81 * sizeof(float), 0,
                            cudaMemcpyDeviceToDevice);

    const int pairs_total = in_sizes[0] / 18;     // B * G^3 / 2
    const int threads = 128;
    const int blocks = (pairs_total + threads - 1) / threads;
    alphaC0_kernel<<<blocks, threads>>>(alpha, out, pairs_total);
}

// round 14
// speedup vs baseline: 1.0609x; 1.0609x over previous
#include <cuda_runtime.h>

#define G3 (64 * 64 * 64)          // 262144 voxels per batch
#define PAIRS_PER_B (G3 / 2)       // 131072 voxel pairs per batch

typedef unsigned long long u64;

__device__ __forceinline__ u64 f2fma(u64 a, u64 b, u64 c) {
    u64 d; asm("fma.rn.f32x2 %0, %1, %2, %3;" : "=l"(d) : "l"(a), "l"(b), "l"(c)); return d;
}
__device__ __forceinline__ u64 f2mul(u64 a, u64 b) {
    u64 d; asm("mul.rn.f32x2 %0, %1, %2;" : "=l"(d) : "l"(a), "l"(b)); return d;
}
__device__ __forceinline__ u64 f2dup(float x) {
    u64 d; asm("mov.b64 %0, {%1, %1};" : "=l"(d) : "f"(x)); return d;
}

// SINGLE-NODE kernel. C0 comes straight from gmem via a per-block reordered
// smem table: c0r[n*3+o][m*3+p] (9 floats per group, padded to 12 so each
// group is 16B-aligned -> 2x LDS.128 + 1x LDS.32 per group = 81 LDS/thread,
// 3x fewer than the naive smem layout). Lane-dup movs are issue-slot free.
__global__ void __launch_bounds__(128, 4)
alphaC0_kernel(const float* __restrict__ alpha,
               const float* __restrict__ C0,
               float* __restrict__ out,
               int pairs_total)
{
    __shared__ float c0r[9][12];
    {
        const int t = threadIdx.x;
        if (t < 108) {
            const int g = t / 12, s = t % 12;        // group (n,o), slot (m,p)
            float val = 0.0f;
            if (s < 9) {
                const int n = g / 3, o = g % 3;
                const int m = s / 3, p = s % 3;
                val = C0[((m * 3 + n) * 3 + o) * 3 + p];
            }
            c0r[g][s] = val;
        }
    }
    __syncthreads();

    const int tid = blockIdx.x * blockDim.x + threadIdx.x;
    if (tid >= pairs_total) return;

    const int b = tid >> 17;                   // / PAIRS_PER_B
    const int v = (tid & (PAIRS_PER_B - 1)) * 2;

    // A2[m][c] = packed { A(v)[m][c], A(v+1)[m][c] }
    u64 A2[3][3];
#pragma unroll
    for (int m = 0; m < 3; m++)
#pragma unroll
        for (int c = 0; c < 3; c++)
            A2[m][c] = *reinterpret_cast<const u64*>(
                &alpha[(size_t)((b * 3 + m) * 3 + c) * G3 + v]);

    const char* outb0 = reinterpret_cast<const char*>(out)
                      + ((size_t)b * 81 * G3 + v) * sizeof(float);

#pragma unroll 1
    for (int i = 0; i < 3; i++) {
        u64 a0, a1, a2;
        if (i == 0)      { a0 = A2[0][0]; a1 = A2[1][0]; a2 = A2[2][0]; }
        else if (i == 1) { a0 = A2[0][1]; a1 = A2[1][1]; a2 = A2[2][1]; }
        else             { a0 = A2[0][2]; a1 = A2[1][2]; a2 = A2[2][2]; }

        // Fused stage1+2: T2[j][o][p] = sum_n A[n][j] * (sum_m a_m C0[m][n][o][p])
        // For each (o,n): one 9-float group read (vectorized LDS), build
        // t1d[p] = sum_m a_m c0, accumulate into T2 over n.
        u64 T2[27];
#pragma unroll
        for (int o = 0; o < 3; o++) {
#pragma unroll
            for (int n = 0; n < 3; n++) {
                const float* grp = c0r[n * 3 + o];
                float4 q0 = *reinterpret_cast<const float4*>(grp);      // (m0p0..m1p0)
                float4 q1 = *reinterpret_cast<const float4*>(grp + 4);  // (m1p1..m2p1)
                float  c8 = grp[8];                                     // m2p2
                float c[9] = { q0.x, q0.y, q0.z, q0.w, q1.x, q1.y, q1.z, q1.w, c8 };

                u64 t1d[3];
#pragma unroll
                for (int p = 0; p < 3; p++) {
                    t1d[p] = f2fma(a0, f2dup(c[p]),
                             f2fma(a1, f2dup(c[3 + p]),
                             f2mul(a2, f2dup(c[6 + p]))));
                }
#pragma unroll
                for (int j = 0; j < 3; j++)
#pragma unroll
                    for (int p = 0; p < 3; p++) {
                        if (n == 0)
                            T2[(j * 3 + o) * 3 + p] = f2mul(A2[0][j], t1d[p]);
                        else
                            T2[(j * 3 + o) * 3 + p] =
                                f2fma(A2[n][j], t1d[p], T2[(j * 3 + o) * 3 + p]);
                    }
            }
        }

        // Fused stage3+4: per (j,k) build t3[p], emit 3 STG.64 immediately
        const char* outb = outb0 + (size_t)(i * 27) * G3 * sizeof(float);
#pragma unroll
        for (int j = 0; j < 3; j++) {
#pragma unroll
            for (int k = 0; k < 3; k++) {
                u64 t3[3];
#pragma unroll
                for (int p = 0; p < 3; p++) {
                    t3[p] = f2fma(A2[0][k], T2[(j * 3 + 0) * 3 + p],
                            f2fma(A2[1][k], T2[(j * 3 + 1) * 3 + p],
                            f2mul(A2[2][k], T2[(j * 3 + 2) * 3 + p])));
                }
#pragma unroll
                for (int l = 0; l < 3; l++) {
                    *reinterpret_cast<u64*>(const_cast<char*>(
                        outb + (size_t)((j * 3 + k) * 3 + l) * G3 * sizeof(float))) =
                        f2fma(A2[0][l], t3[0],
                        f2fma(A2[1][l], t3[1],
                        f2mul(A2[2][l], t3[2])));
                }
            }
        }
    }
}

extern "C" void kernel_launch(void* const* d_in, const int* in_sizes, int n_in,
                              void* d_out, int out_size)
{
    const float* alpha = (const float*)d_in[0];   // (B,3,3,G,G,G) float32
    const float* C0    = (const float*)d_in[1];   // (3,3,3,3) float32
    float* out         = (float*)d_out;           // (B,3,3,3,3,G,G,G) float32

    const int pairs_total = in_sizes[0] / 18;     // B * G^3 / 2
    const int threads = 128;
    const int blocks = (pairs_total + threads - 1) / threads;
    alphaC0_kernel<<<blocks, threads>>>(alpha, C0, out, pairs_total);
}